// round 1
// baseline (speedup 1.0000x reference)
#include <cuda_runtime.h>
#include <math.h>

#define BD  2
#define TT  2048
#define CC  2048
#define HH  32
#define HKVN 8
#define DDIM 64
#define GRP 4

// Scratch (allocation-free rule: __device__ globals)
__device__ float g_Q[BD * TT * CC];            // [b,t,h,d]
__device__ float g_K[BD * TT * HKVN * DDIM];   // [b,t,hkv,d]
__device__ float g_V[BD * TT * HKVN * DDIM];
__device__ float g_AO[BD * TT * CC];           // [b,t,h,d]

// ---------------------------------------------------------------------------
// NT GEMM: C[M,N] = A[M,K] * W[N,K]^T   (both row-major, K contiguous)
// 128x128 tile, BK=8, 256 threads, 8x8 per thread.
// ---------------------------------------------------------------------------
__global__ __launch_bounds__(256, 2)
void gemm_nt(const float* __restrict__ A, const float* __restrict__ W,
             float* __restrict__ C, int M, int N, int K) {
    __shared__ float As[8][128];   // k-major
    __shared__ float Bs[8][128];
    const int tid = threadIdx.x;
    const int tx = tid & 15;
    const int ty = tid >> 4;
    const int m0 = blockIdx.y * 128;
    const int n0 = blockIdx.x * 128;
    const int lrow = tid >> 1;          // 0..127
    const int lk = (tid & 1) * 4;       // 0 or 4
    const float* Ag = A + (size_t)(m0 + lrow) * K + lk;
    const float* Wg = W + (size_t)(n0 + lrow) * K + lk;

    float acc[8][8];
#pragma unroll
    for (int i = 0; i < 8; i++)
#pragma unroll
        for (int j = 0; j < 8; j++) acc[i][j] = 0.f;

    for (int kt = 0; kt < K; kt += 8) {
        float4 av = *(const float4*)(Ag + kt);
        float4 wv = *(const float4*)(Wg + kt);
        __syncthreads();
        As[lk + 0][lrow] = av.x;
        As[lk + 1][lrow] = av.y;
        As[lk + 2][lrow] = av.z;
        As[lk + 3][lrow] = av.w;
        Bs[lk + 0][lrow] = wv.x;
        Bs[lk + 1][lrow] = wv.y;
        Bs[lk + 2][lrow] = wv.z;
        Bs[lk + 3][lrow] = wv.w;
        __syncthreads();
#pragma unroll
        for (int kk = 0; kk < 8; kk++) {
            float a[8], b[8];
            *(float4*)(a)     = *(const float4*)(&As[kk][ty * 8]);
            *(float4*)(a + 4) = *(const float4*)(&As[kk][ty * 8 + 4]);
            *(float4*)(b)     = *(const float4*)(&Bs[kk][tx * 8]);
            *(float4*)(b + 4) = *(const float4*)(&Bs[kk][tx * 8 + 4]);
#pragma unroll
            for (int i = 0; i < 8; i++)
#pragma unroll
                for (int j = 0; j < 8; j++) acc[i][j] += a[i] * b[j];
        }
    }
#pragma unroll
    for (int i = 0; i < 8; i++) {
        float* Cp = C + (size_t)(m0 + ty * 8 + i) * N + n0 + tx * 8;
        *(float4*)(Cp)     = make_float4(acc[i][0], acc[i][1], acc[i][2], acc[i][3]);
        *(float4*)(Cp + 4) = make_float4(acc[i][4], acc[i][5], acc[i][6], acc[i][7]);
    }
}

// ---------------------------------------------------------------------------
// RoPE (in-place) on X laid out [b, t, nheads, 64].
// Thread handles rotation pair (i, i+32), i in [0,32).
// ---------------------------------------------------------------------------
__global__ void rope_kernel(float* __restrict__ X, int nheads, int total) {
    int idx = blockIdx.x * blockDim.x + threadIdx.x;
    if (idx >= total) return;
    int i = idx & 31;
    int h = (idx >> 5) % nheads;
    int t = (idx / (32 * nheads)) % TT;
    int b = idx / (32 * nheads * TT);
    float inv_freq = powf(10000.0f, -(float)(2 * i) / 64.0f);
    float ang = (float)t * inv_freq;
    float c = cosf(ang);
    float s = sinf(ang);
    size_t base = ((size_t)(b * TT + t) * nheads + h) * 64;
    float x1 = X[base + i];
    float x2 = X[base + i + 32];
    X[base + i]      = x1 * c - x2 * s;   // x1*cos + rotate_half(-x2)*sin
    X[base + i + 32] = x2 * c + x1 * s;
}

// ---------------------------------------------------------------------------
// Causal flash attention, fp32, online softmax.
// Grid: (T/64, B*H). 256 threads. 64 queries per CTA, KV blocks of 64.
// SMEM: Qs[d][r] 64x64, Ks[d][c] 64x64, Vs[c][d] 64x68(pad), Ps[c][r] 64x65(pad)
// Thread (tx,ty) owns S rows r0=ty*4..+3, cols c0=tx*4..+3 and O cols d0=tx*4..+3.
// ---------------------------------------------------------------------------
#define FL_QS 0
#define FL_KS 4096
#define FL_VS 8192
#define FL_PS (8192 + 64 * 68)
#define FL_SMEM_FLOATS (8192 + 64 * 68 + 64 * 65)
#define FL_SMEM_BYTES (FL_SMEM_FLOATS * 4)

__global__ __launch_bounds__(256)
void flash_kernel(const float* __restrict__ Q, const float* __restrict__ K,
                  const float* __restrict__ V, float* __restrict__ AO) {
    extern __shared__ float sm[];
    float* Qs = sm + FL_QS;
    float* Ks = sm + FL_KS;
    float* Vs = sm + FL_VS;   // stride 68
    float* Ps = sm + FL_PS;   // stride 65

    const int tid = threadIdx.x;
    const int tx = tid & 15;
    const int ty = tid >> 4;
    const int qb = blockIdx.x;
    const int bh = blockIdx.y;
    const int b = bh >> 5;     // / H
    const int h = bh & 31;
    const int hk = h >> 2;     // / G
    const int q0 = qb * 64;

    const int lr = tid & 63;   // row for cooperative loads (conflict-free stores)
    const int lg = tid >> 6;   // 0..3 -> which 16-dim chunk

    // Load Q tile transposed: Qs[d][r]
    {
        const float* Qg = Q + ((size_t)(b * TT + q0 + lr) * HH + h) * DDIM;
#pragma unroll
        for (int i = 0; i < 4; i++) {
            int d0 = lg * 16 + i * 4;
            float4 v = *(const float4*)(Qg + d0);
            Qs[(d0 + 0) * 64 + lr] = v.x;
            Qs[(d0 + 1) * 64 + lr] = v.y;
            Qs[(d0 + 2) * 64 + lr] = v.z;
            Qs[(d0 + 3) * 64 + lr] = v.w;
        }
    }

    float m_[4], l_[4], o_[4][4];
#pragma unroll
    for (int i = 0; i < 4; i++) {
        m_[i] = -INFINITY;
        l_[i] = 0.f;
#pragma unroll
        for (int j = 0; j < 4; j++) o_[i][j] = 0.f;
    }
    const float scale = 0.125f;   // 1/sqrt(64)

    for (int kb = 0; kb <= qb; kb++) {
        const int k0 = kb * 64;
        __syncthreads();   // previous iteration's reads of Ks/Vs/Ps done
        {
            const float* Kg = K + ((size_t)(b * TT + k0 + lr) * HKVN + hk) * DDIM;
            const float* Vg = V + ((size_t)(b * TT + k0 + lr) * HKVN + hk) * DDIM;
#pragma unroll
            for (int i = 0; i < 4; i++) {
                int d0 = lg * 16 + i * 4;
                float4 kv = *(const float4*)(Kg + d0);
                Ks[(d0 + 0) * 64 + lr] = kv.x;
                Ks[(d0 + 1) * 64 + lr] = kv.y;
                Ks[(d0 + 2) * 64 + lr] = kv.z;
                Ks[(d0 + 3) * 64 + lr] = kv.w;
                *(float4*)(&Vs[lr * 68 + d0]) = *(const float4*)(Vg + d0);
            }
        }
        __syncthreads();

        // S = Q K^T (4x4 per thread)
        float s[4][4];
#pragma unroll
        for (int i = 0; i < 4; i++)
#pragma unroll
            for (int j = 0; j < 4; j++) s[i][j] = 0.f;

#pragma unroll 8
        for (int kk = 0; kk < 64; kk++) {
            float4 af = *(const float4*)(&Qs[kk * 64 + ty * 4]);
            float4 bf = *(const float4*)(&Ks[kk * 64 + tx * 4]);
            float a[4] = {af.x, af.y, af.z, af.w};
            float bb[4] = {bf.x, bf.y, bf.z, bf.w};
#pragma unroll
            for (int i = 0; i < 4; i++)
#pragma unroll
                for (int j = 0; j < 4; j++) s[i][j] += a[i] * bb[j];
        }

        const bool diag = (kb == qb);
#pragma unroll
        for (int i = 0; i < 4; i++) {
            int qr = q0 + ty * 4 + i;
            float rm = -INFINITY;
#pragma unroll
            for (int j = 0; j < 4; j++) {
                float v = s[i][j] * scale;
                if (diag && (k0 + tx * 4 + j) > qr) v = -INFINITY;
                s[i][j] = v;
                rm = fmaxf(rm, v);
            }
#pragma unroll
            for (int mm = 8; mm >= 1; mm >>= 1)
                rm = fmaxf(rm, __shfl_xor_sync(0xffffffffu, rm, mm));
            float mn = fmaxf(m_[i], rm);
            float alpha = expf(m_[i] - mn);
            float rs = 0.f;
#pragma unroll
            for (int j = 0; j < 4; j++) {
                float p = expf(s[i][j] - mn);
                s[i][j] = p;
                rs += p;
            }
#pragma unroll
            for (int mm = 8; mm >= 1; mm >>= 1)
                rs += __shfl_xor_sync(0xffffffffu, rs, mm);
            l_[i] = l_[i] * alpha + rs;
            m_[i] = mn;
#pragma unroll
            for (int j = 0; j < 4; j++) o_[i][j] *= alpha;
        }

        // Stage P transposed: Ps[c][r] (stride 65 to dodge bank conflicts)
#pragma unroll
        for (int i = 0; i < 4; i++)
#pragma unroll
            for (int j = 0; j < 4; j++)
                Ps[(tx * 4 + j) * 65 + ty * 4 + i] = s[i][j];
        __syncthreads();

        // O += P V  (4x4 per thread)
        for (int c = 0; c < 64; c++) {
            float p0 = Ps[c * 65 + ty * 4 + 0];
            float p1 = Ps[c * 65 + ty * 4 + 1];
            float p2 = Ps[c * 65 + ty * 4 + 2];
            float p3 = Ps[c * 65 + ty * 4 + 3];
            float4 vf = *(const float4*)(&Vs[c * 68 + tx * 4]);
            float vv[4] = {vf.x, vf.y, vf.z, vf.w};
            float p[4] = {p0, p1, p2, p3};
#pragma unroll
            for (int i = 0; i < 4; i++)
#pragma unroll
                for (int j = 0; j < 4; j++) o_[i][j] += p[i] * vv[j];
        }
    }

    // Epilogue: normalize and write AO[b, t, h*64 + d]
#pragma unroll
    for (int i = 0; i < 4; i++) {
        float inv = 1.0f / l_[i];
        int t = q0 + ty * 4 + i;
        float* Op = AO + (size_t)(b * TT + t) * CC + h * 64 + tx * 4;
        *(float4*)Op = make_float4(o_[i][0] * inv, o_[i][1] * inv,
                                   o_[i][2] * inv, o_[i][3] * inv);
    }
}

// ---------------------------------------------------------------------------
extern "C" void kernel_launch(void* const* d_in, const int* in_sizes, int n_in,
                              void* d_out, int out_size) {
    const float* x  = (const float*)d_in[0];
    const float* Wq = (const float*)d_in[1];
    const float* Wk = (const float*)d_in[2];
    const float* Wv = (const float*)d_in[3];
    const float* Wo = (const float*)d_in[4];
    float* out = (float*)d_out;

    float *pQ, *pK, *pV, *pAO;
    cudaGetSymbolAddress((void**)&pQ,  g_Q);
    cudaGetSymbolAddress((void**)&pK,  g_K);
    cudaGetSymbolAddress((void**)&pV,  g_V);
    cudaGetSymbolAddress((void**)&pAO, g_AO);

    cudaFuncSetAttribute(flash_kernel, cudaFuncAttributeMaxDynamicSharedMemorySize,
                         FL_SMEM_BYTES);

    dim3 blk(256);
    // QKV projections
    gemm_nt<<<dim3(16, 32), blk>>>(x, Wq, pQ, BD * TT, CC, CC);
    gemm_nt<<<dim3(4, 32),  blk>>>(x, Wk, pK, BD * TT, HKVN * DDIM, CC);
    gemm_nt<<<dim3(4, 32),  blk>>>(x, Wv, pV, BD * TT, HKVN * DDIM, CC);

    // RoPE
    int totQ = BD * TT * HH * 32;
    int totK = BD * TT * HKVN * 32;
    rope_kernel<<<(totQ + 255) / 256, 256>>>(pQ, HH, totQ);
    rope_kernel<<<(totK + 255) / 256, 256>>>(pK, HKVN, totK);

    // Causal flash attention
    flash_kernel<<<dim3(TT / 64, BD * HH), blk, FL_SMEM_BYTES>>>(pQ, pK, pV, pAO);

    // Output projection
    gemm_nt<<<dim3(16, 32), blk>>>(pAO, Wo, out, BD * TT, CC, CC);
}

// round 3
// speedup vs baseline: 1.7924x; 1.7924x over previous
#include <cuda_runtime.h>
#include <math.h>
#include <stdint.h>

#define BD  2
#define TT  2048
#define CC  2048
#define HH  32
#define HKVN 8
#define DDIM 64
#define GRP 4

// Scratch (allocation-free rule: __device__ globals)
__device__ float g_Q[BD * TT * CC];            // [b,t,h,d]
__device__ float g_K[BD * TT * HKVN * DDIM];   // [b,t,hkv,d]
__device__ float g_V[BD * TT * HKVN * DDIM];
__device__ float g_AO[BD * TT * CC];           // [b,t,h,d]

// ===========================================================================
// tf32 tensor-core NT GEMM: C[M,N] = A[M,K] * W[N,K]^T  (row-major, K contig)
// 128x128x32 tiles, 256 threads (8 warps, 2x4), warp tile 64x32,
// mma.sync.m16n8k8.tf32, 2-stage cp.async pipeline.
// SMEM row stride 36 floats -> fragment loads hit 32 distinct banks.
// ===========================================================================
#define GBM 128
#define GBN 128
#define GBK 32
#define GPAD 36
#define STAGE_FLOATS (128 * GPAD)
#define GEMM_SMEM_BYTES (4 * STAGE_FLOATS * 4)   // A(2 stages) + B(2 stages)

__device__ __forceinline__ uint32_t f2tf32(float x) {
    uint32_t u;
    asm("cvt.rna.tf32.f32 %0, %1;" : "=r"(u) : "f"(x));
    return u;
}

__device__ __forceinline__ void mma_tf32(float c[4], const uint32_t a[4],
                                         const uint32_t b[2]) {
    asm volatile(
        "mma.sync.aligned.m16n8k8.row.col.f32.tf32.tf32.f32 "
        "{%0,%1,%2,%3}, {%4,%5,%6,%7}, {%8,%9}, {%0,%1,%2,%3};\n"
        : "+f"(c[0]), "+f"(c[1]), "+f"(c[2]), "+f"(c[3])
        : "r"(a[0]), "r"(a[1]), "r"(a[2]), "r"(a[3]), "r"(b[0]), "r"(b[1]));
}

__global__ __launch_bounds__(256)
void gemm_tf32(const float* __restrict__ A, const float* __restrict__ W,
               float* __restrict__ C, int M, int N, int K) {
    extern __shared__ float sm[];
    float* As = sm;                      // [2][128][36]
    float* Bs = sm + 2 * STAGE_FLOATS;   // [2][128][36]

    const int tid = threadIdx.x;
    const int warp = tid >> 5, lane = tid & 31;
    const int wm = warp >> 2, wn = warp & 3;
    const int g = lane >> 2, tg = lane & 3;
    const int m0 = blockIdx.y * GBM, n0 = blockIdx.x * GBN;

    const float* Ag = A + (size_t)m0 * K;
    const float* Wg = W + (size_t)n0 * K;

    float acc[4][4][4];
#pragma unroll
    for (int mt = 0; mt < 4; mt++)
#pragma unroll
        for (int nt = 0; nt < 4; nt++)
#pragma unroll
            for (int v = 0; v < 4; v++) acc[mt][nt][v] = 0.f;

    const int ntiles = K / GBK;

    auto load_tile = [&](int kt, int s) {
#pragma unroll
        for (int i = 0; i < 4; i++) {
            int idx = tid + i * 256;
            int row = idx >> 3;
            int kq = (idx & 7) * 4;
            uint32_t da = (uint32_t)__cvta_generic_to_shared(
                &As[s * STAGE_FLOATS + row * GPAD + kq]);
            const float* sa = Ag + (size_t)row * K + kt * GBK + kq;
            asm volatile("cp.async.cg.shared.global [%0], [%1], 16;\n" ::
                         "r"(da), "l"(sa));
            uint32_t db = (uint32_t)__cvta_generic_to_shared(
                &Bs[s * STAGE_FLOATS + row * GPAD + kq]);
            const float* sb = Wg + (size_t)row * K + kt * GBK + kq;
            asm volatile("cp.async.cg.shared.global [%0], [%1], 16;\n" ::
                         "r"(db), "l"(sb));
        }
        asm volatile("cp.async.commit_group;\n");
    };

    load_tile(0, 0);

    for (int kt = 0; kt < ntiles; kt++) {
        const int s = kt & 1;
        if (kt + 1 < ntiles) {
            load_tile(kt + 1, (kt + 1) & 1);
            asm volatile("cp.async.wait_group 1;\n");
        } else {
            asm volatile("cp.async.wait_group 0;\n");
        }
        __syncthreads();

        const float* Asl = As + s * STAGE_FLOATS;
        const float* Bsl = Bs + s * STAGE_FLOATS;

#pragma unroll
        for (int ks = 0; ks < 4; ks++) {
            const int k = ks * 8;
            uint32_t af[4][4];
#pragma unroll
            for (int mt = 0; mt < 4; mt++) {
                int mb = wm * 64 + mt * 16;
                af[mt][0] = f2tf32(Asl[(mb + g) * GPAD + k + tg]);
                af[mt][1] = f2tf32(Asl[(mb + g + 8) * GPAD + k + tg]);
                af[mt][2] = f2tf32(Asl[(mb + g) * GPAD + k + tg + 4]);
                af[mt][3] = f2tf32(Asl[(mb + g + 8) * GPAD + k + tg + 4]);
            }
            uint32_t bf[4][2];
#pragma unroll
            for (int nt = 0; nt < 4; nt++) {
                int nb = wn * 32 + nt * 8;
                bf[nt][0] = f2tf32(Bsl[(nb + g) * GPAD + k + tg]);
                bf[nt][1] = f2tf32(Bsl[(nb + g) * GPAD + k + tg + 4]);
            }
#pragma unroll
            for (int mt = 0; mt < 4; mt++)
#pragma unroll
                for (int nt = 0; nt < 4; nt++)
                    mma_tf32(acc[mt][nt], af[mt], bf[nt]);
        }
        __syncthreads();
    }

    // Epilogue: c0/c1 at (row g, col tg*2..+1), c2/c3 at row g+8
#pragma unroll
    for (int mt = 0; mt < 4; mt++) {
#pragma unroll
        for (int nt = 0; nt < 4; nt++) {
            int r0 = m0 + wm * 64 + mt * 16 + g;
            int c0 = n0 + wn * 32 + nt * 8 + tg * 2;
            *(float2*)(&C[(size_t)r0 * N + c0]) =
                make_float2(acc[mt][nt][0], acc[mt][nt][1]);
            *(float2*)(&C[(size_t)(r0 + 8) * N + c0]) =
                make_float2(acc[mt][nt][2], acc[mt][nt][3]);
        }
    }
}

// ---------------------------------------------------------------------------
// RoPE (in-place) on X laid out [b, t, nheads, 64].
// ---------------------------------------------------------------------------
__global__ void rope_kernel(float* __restrict__ X, int nheads, int total) {
    int idx = blockIdx.x * blockDim.x + threadIdx.x;
    if (idx >= total) return;
    int i = idx & 31;
    int h = (idx >> 5) % nheads;
    int t = (idx / (32 * nheads)) % TT;
    int b = idx / (32 * nheads * TT);
    float inv_freq = powf(10000.0f, -(float)(2 * i) / 64.0f);
    float ang = (float)t * inv_freq;
    float c = cosf(ang);
    float s = sinf(ang);
    size_t base = ((size_t)(b * TT + t) * nheads + h) * 64;
    float x1 = X[base + i];
    float x2 = X[base + i + 32];
    X[base + i]      = x1 * c - x2 * s;
    X[base + i + 32] = x2 * c + x1 * s;
}

// ---------------------------------------------------------------------------
// Causal flash attention, fp32, online softmax (unchanged, passing).
// ---------------------------------------------------------------------------
#define FL_QS 0
#define FL_KS 4096
#define FL_VS 8192
#define FL_PS (8192 + 64 * 68)
#define FL_SMEM_FLOATS (8192 + 64 * 68 + 64 * 65)
#define FL_SMEM_BYTES (FL_SMEM_FLOATS * 4)

__global__ __launch_bounds__(256)
void flash_kernel(const float* __restrict__ Q, const float* __restrict__ K,
                  const float* __restrict__ V, float* __restrict__ AO) {
    extern __shared__ float sm[];
    float* Qs = sm + FL_QS;
    float* Ks = sm + FL_KS;
    float* Vs = sm + FL_VS;   // stride 68
    float* Ps = sm + FL_PS;   // stride 65

    const int tid = threadIdx.x;
    const int tx = tid & 15;
    const int ty = tid >> 4;
    const int qb = blockIdx.x;
    const int bh = blockIdx.y;
    const int b = bh >> 5;
    const int h = bh & 31;
    const int hk = h >> 2;
    const int q0 = qb * 64;

    const int lr = tid & 63;
    const int lg = tid >> 6;

    {
        const float* Qg = Q + ((size_t)(b * TT + q0 + lr) * HH + h) * DDIM;
#pragma unroll
        for (int i = 0; i < 4; i++) {
            int d0 = lg * 16 + i * 4;
            float4 v = *(const float4*)(Qg + d0);
            Qs[(d0 + 0) * 64 + lr] = v.x;
            Qs[(d0 + 1) * 64 + lr] = v.y;
            Qs[(d0 + 2) * 64 + lr] = v.z;
            Qs[(d0 + 3) * 64 + lr] = v.w;
        }
    }

    float m_[4], l_[4], o_[4][4];
#pragma unroll
    for (int i = 0; i < 4; i++) {
        m_[i] = -INFINITY;
        l_[i] = 0.f;
#pragma unroll
        for (int j = 0; j < 4; j++) o_[i][j] = 0.f;
    }
    const float scale = 0.125f;

    for (int kb = 0; kb <= qb; kb++) {
        const int k0 = kb * 64;
        __syncthreads();
        {
            const float* Kg = K + ((size_t)(b * TT + k0 + lr) * HKVN + hk) * DDIM;
            const float* Vg = V + ((size_t)(b * TT + k0 + lr) * HKVN + hk) * DDIM;
#pragma unroll
            for (int i = 0; i < 4; i++) {
                int d0 = lg * 16 + i * 4;
                float4 kv = *(const float4*)(Kg + d0);
                Ks[(d0 + 0) * 64 + lr] = kv.x;
                Ks[(d0 + 1) * 64 + lr] = kv.y;
                Ks[(d0 + 2) * 64 + lr] = kv.z;
                Ks[(d0 + 3) * 64 + lr] = kv.w;
                *(float4*)(&Vs[lr * 68 + d0]) = *(const float4*)(Vg + d0);
            }
        }
        __syncthreads();

        float s[4][4];
#pragma unroll
        for (int i = 0; i < 4; i++)
#pragma unroll
            for (int j = 0; j < 4; j++) s[i][j] = 0.f;

#pragma unroll 8
        for (int kk = 0; kk < 64; kk++) {
            float4 af = *(const float4*)(&Qs[kk * 64 + ty * 4]);
            float4 bf = *(const float4*)(&Ks[kk * 64 + tx * 4]);
            float a[4] = {af.x, af.y, af.z, af.w};
            float bb[4] = {bf.x, bf.y, bf.z, bf.w};
#pragma unroll
            for (int i = 0; i < 4; i++)
#pragma unroll
                for (int j = 0; j < 4; j++) s[i][j] += a[i] * bb[j];
        }

        const bool diag = (kb == qb);
#pragma unroll
        for (int i = 0; i < 4; i++) {
            int qr = q0 + ty * 4 + i;
            float rm = -INFINITY;
#pragma unroll
            for (int j = 0; j < 4; j++) {
                float v = s[i][j] * scale;
                if (diag && (k0 + tx * 4 + j) > qr) v = -INFINITY;
                s[i][j] = v;
                rm = fmaxf(rm, v);
            }
#pragma unroll
            for (int mm = 8; mm >= 1; mm >>= 1)
                rm = fmaxf(rm, __shfl_xor_sync(0xffffffffu, rm, mm));
            float mn = fmaxf(m_[i], rm);
            float alpha = expf(m_[i] - mn);
            float rs = 0.f;
#pragma unroll
            for (int j = 0; j < 4; j++) {
                float p = expf(s[i][j] - mn);
                s[i][j] = p;
                rs += p;
            }
#pragma unroll
            for (int mm = 8; mm >= 1; mm >>= 1)
                rs += __shfl_xor_sync(0xffffffffu, rs, mm);
            l_[i] = l_[i] * alpha + rs;
            m_[i] = mn;
#pragma unroll
            for (int j = 0; j < 4; j++) o_[i][j] *= alpha;
        }

#pragma unroll
        for (int i = 0; i < 4; i++)
#pragma unroll
            for (int j = 0; j < 4; j++)
                Ps[(tx * 4 + j) * 65 + ty * 4 + i] = s[i][j];
        __syncthreads();

        for (int c = 0; c < 64; c++) {
            float p0 = Ps[c * 65 + ty * 4 + 0];
            float p1 = Ps[c * 65 + ty * 4 + 1];
            float p2 = Ps[c * 65 + ty * 4 + 2];
            float p3 = Ps[c * 65 + ty * 4 + 3];
            float4 vf = *(const float4*)(&Vs[c * 68 + tx * 4]);
            float vv[4] = {vf.x, vf.y, vf.z, vf.w};
            float p[4] = {p0, p1, p2, p3};
#pragma unroll
            for (int i = 0; i < 4; i++)
#pragma unroll
                for (int j = 0; j < 4; j++) o_[i][j] += p[i] * vv[j];
        }
    }

#pragma unroll
    for (int i = 0; i < 4; i++) {
        float inv = 1.0f / l_[i];
        int t = q0 + ty * 4 + i;
        float* Op = AO + (size_t)(b * TT + t) * CC + h * 64 + tx * 4;
        *(float4*)Op = make_float4(o_[i][0] * inv, o_[i][1] * inv,
                                   o_[i][2] * inv, o_[i][3] * inv);
    }
}

// ---------------------------------------------------------------------------
extern "C" void kernel_launch(void* const* d_in, const int* in_sizes, int n_in,
                              void* d_out, int out_size) {
    const float* x  = (const float*)d_in[0];
    const float* Wq = (const float*)d_in[1];
    const float* Wk = (const float*)d_in[2];
    const float* Wv = (const float*)d_in[3];
    const float* Wo = (const float*)d_in[4];
    float* out = (float*)d_out;

    float *pQ, *pK, *pV, *pAO;
    cudaGetSymbolAddress((void**)&pQ,  g_Q);
    cudaGetSymbolAddress((void**)&pK,  g_K);
    cudaGetSymbolAddress((void**)&pV,  g_V);
    cudaGetSymbolAddress((void**)&pAO, g_AO);

    cudaFuncSetAttribute(gemm_tf32, cudaFuncAttributeMaxDynamicSharedMemorySize,
                         GEMM_SMEM_BYTES);
    cudaFuncSetAttribute(flash_kernel, cudaFuncAttributeMaxDynamicSharedMemorySize,
                         FL_SMEM_BYTES);

    dim3 blk(256);
    // QKV projections (tensor cores, tf32)
    gemm_tf32<<<dim3(16, 32), blk, GEMM_SMEM_BYTES>>>(x, Wq, pQ, BD * TT, CC, CC);
    gemm_tf32<<<dim3(4, 32),  blk, GEMM_SMEM_BYTES>>>(x, Wk, pK, BD * TT, HKVN * DDIM, CC);
    gemm_tf32<<<dim3(4, 32),  blk, GEMM_SMEM_BYTES>>>(x, Wv, pV, BD * TT, HKVN * DDIM, CC);

    // RoPE
    int totQ = BD * TT * HH * 32;
    int totK = BD * TT * HKVN * 32;
    rope_kernel<<<(totQ + 255) / 256, 256>>>(pQ, HH, totQ);
    rope_kernel<<<(totK + 255) / 256, 256>>>(pK, HKVN, totK);

    // Causal flash attention
    flash_kernel<<<dim3(TT / 64, BD * HH), blk, FL_SMEM_BYTES>>>(pQ, pK, pV, pAO);

    // Output projection
    gemm_tf32<<<dim3(16, 32), blk, GEMM_SMEM_BYTES>>>(pAO, Wo, out, BD * TT, CC, CC);
}

// round 5
// speedup vs baseline: 3.0610x; 1.7078x over previous
#include <cuda_runtime.h>
#include <math.h>
#include <stdint.h>

#define BD  2
#define TT  2048
#define CC  2048
#define HH  32
#define HKVN 8
#define DDIM 64
#define GRP 4

// Scratch (allocation-free rule: __device__ globals)
__device__ float g_Q[BD * TT * CC];            // [b,t,h,d]
__device__ float g_K[BD * TT * HKVN * DDIM];   // [b,t,hkv,d]
__device__ float g_V[BD * TT * HKVN * DDIM];
__device__ float g_AO[BD * TT * CC];           // [b,t,h,d]

__device__ __forceinline__ uint32_t f2tf32(float x) {
    uint32_t u;
    asm("cvt.rna.tf32.f32 %0, %1;" : "=r"(u) : "f"(x));
    return u;
}

__device__ __forceinline__ void mma_tf32(float c[4], const uint32_t a[4],
                                         const uint32_t b[2]) {
    asm volatile(
        "mma.sync.aligned.m16n8k8.row.col.f32.tf32.tf32.f32 "
        "{%0,%1,%2,%3}, {%4,%5,%6,%7}, {%8,%9}, {%0,%1,%2,%3};\n"
        : "+f"(c[0]), "+f"(c[1]), "+f"(c[2]), "+f"(c[3])
        : "r"(a[0]), "r"(a[1]), "r"(a[2]), "r"(a[3]), "r"(b[0]), "r"(b[1]));
}

// exp2 on the FMA pipe (no MUFU). |err| < 3e-6 rel. Input clamped to >= -126.
__device__ __forceinline__ float fexp2(float x) {
    x = fmaxf(x, -126.0f);
    float r = rintf(x);
    float f = x - r;               // [-0.5, 0.5]
    float p = 1.3333558e-3f;
    p = fmaf(p, f, 9.6181291e-3f);
    p = fmaf(p, f, 5.5504109e-2f);
    p = fmaf(p, f, 2.4022651e-1f);
    p = fmaf(p, f, 6.9314718e-1f);
    p = fmaf(p, f, 1.0f);
    int e = (int)r;
    return p * __int_as_float((e + 127) << 23);
}

// ===========================================================================
// tf32 tensor-core NT GEMM (unchanged from R2, passing)
// ===========================================================================
#define GBM 128
#define GBN 128
#define GBK 32
#define GPAD 36
#define STAGE_FLOATS (128 * GPAD)
#define GEMM_SMEM_BYTES (4 * STAGE_FLOATS * 4)

__global__ __launch_bounds__(256)
void gemm_tf32(const float* __restrict__ A, const float* __restrict__ W,
               float* __restrict__ C, int M, int N, int K) {
    extern __shared__ float sm[];
    float* As = sm;
    float* Bs = sm + 2 * STAGE_FLOATS;

    const int tid = threadIdx.x;
    const int warp = tid >> 5, lane = tid & 31;
    const int wm = warp >> 2, wn = warp & 3;
    const int g = lane >> 2, tg = lane & 3;
    const int m0 = blockIdx.y * GBM, n0 = blockIdx.x * GBN;

    const float* Ag = A + (size_t)m0 * K;
    const float* Wg = W + (size_t)n0 * K;

    float acc[4][4][4];
#pragma unroll
    for (int mt = 0; mt < 4; mt++)
#pragma unroll
        for (int nt = 0; nt < 4; nt++)
#pragma unroll
            for (int v = 0; v < 4; v++) acc[mt][nt][v] = 0.f;

    const int ntiles = K / GBK;

    auto load_tile = [&](int kt, int s) {
#pragma unroll
        for (int i = 0; i < 4; i++) {
            int idx = tid + i * 256;
            int row = idx >> 3;
            int kq = (idx & 7) * 4;
            uint32_t da = (uint32_t)__cvta_generic_to_shared(
                &As[s * STAGE_FLOATS + row * GPAD + kq]);
            const float* sa = Ag + (size_t)row * K + kt * GBK + kq;
            asm volatile("cp.async.cg.shared.global [%0], [%1], 16;\n" ::
                         "r"(da), "l"(sa));
            uint32_t db = (uint32_t)__cvta_generic_to_shared(
                &Bs[s * STAGE_FLOATS + row * GPAD + kq]);
            const float* sb = Wg + (size_t)row * K + kt * GBK + kq;
            asm volatile("cp.async.cg.shared.global [%0], [%1], 16;\n" ::
                         "r"(db), "l"(sb));
        }
        asm volatile("cp.async.commit_group;\n");
    };

    load_tile(0, 0);

    for (int kt = 0; kt < ntiles; kt++) {
        const int s = kt & 1;
        if (kt + 1 < ntiles) {
            load_tile(kt + 1, (kt + 1) & 1);
            asm volatile("cp.async.wait_group 1;\n");
        } else {
            asm volatile("cp.async.wait_group 0;\n");
        }
        __syncthreads();

        const float* Asl = As + s * STAGE_FLOATS;
        const float* Bsl = Bs + s * STAGE_FLOATS;

#pragma unroll
        for (int ks = 0; ks < 4; ks++) {
            const int k = ks * 8;
            uint32_t af[4][4];
#pragma unroll
            for (int mt = 0; mt < 4; mt++) {
                int mb = wm * 64 + mt * 16;
                af[mt][0] = f2tf32(Asl[(mb + g) * GPAD + k + tg]);
                af[mt][1] = f2tf32(Asl[(mb + g + 8) * GPAD + k + tg]);
                af[mt][2] = f2tf32(Asl[(mb + g) * GPAD + k + tg + 4]);
                af[mt][3] = f2tf32(Asl[(mb + g + 8) * GPAD + k + tg + 4]);
            }
            uint32_t bf[4][2];
#pragma unroll
            for (int nt = 0; nt < 4; nt++) {
                int nb = wn * 32 + nt * 8;
                bf[nt][0] = f2tf32(Bsl[(nb + g) * GPAD + k + tg]);
                bf[nt][1] = f2tf32(Bsl[(nb + g) * GPAD + k + tg + 4]);
            }
#pragma unroll
            for (int mt = 0; mt < 4; mt++)
#pragma unroll
                for (int nt = 0; nt < 4; nt++)
                    mma_tf32(acc[mt][nt], af[mt], bf[nt]);
        }
        __syncthreads();
    }

#pragma unroll
    for (int mt = 0; mt < 4; mt++) {
#pragma unroll
        for (int nt = 0; nt < 4; nt++) {
            int r0 = m0 + wm * 64 + mt * 16 + g;
            int c0 = n0 + wn * 32 + nt * 8 + tg * 2;
            *(float2*)(&C[(size_t)r0 * N + c0]) =
                make_float2(acc[mt][nt][0], acc[mt][nt][1]);
            *(float2*)(&C[(size_t)(r0 + 8) * N + c0]) =
                make_float2(acc[mt][nt][2], acc[mt][nt][3]);
        }
    }
}

// ---------------------------------------------------------------------------
// RoPE (in-place) on X laid out [b, t, nheads, 64].
// ---------------------------------------------------------------------------
__global__ void rope_kernel(float* __restrict__ X, int nheads, int total) {
    int idx = blockIdx.x * blockDim.x + threadIdx.x;
    if (idx >= total) return;
    int i = idx & 31;
    int h = (idx >> 5) % nheads;
    int t = (idx / (32 * nheads)) % TT;
    int b = idx / (32 * nheads * TT);
    float inv_freq = powf(10000.0f, -(float)(2 * i) / 64.0f);
    float ang = (float)t * inv_freq;
    float c = cosf(ang);
    float s = sinf(ang);
    size_t base = ((size_t)(b * TT + t) * nheads + h) * 64;
    float x1 = X[base + i];
    float x2 = X[base + i + 32];
    X[base + i]      = x1 * c - x2 * s;
    X[base + i + 32] = x2 * c + x1 * s;
}

// ===========================================================================
// Tensor-core causal flash attention (tf32 mma + FMA-pipe exp2).
// Br=128 rows/CTA, Bc=64 keys/iter, 256 threads (8 warps x 16-row strips).
// Q/K/V pre-converted to tf32 in SMEM; strides chosen conflict-free:
//   Qs[128][68], Ks[64][68], Vs[64][72], Ps[128][68]  (Ps is warp-private)
// ===========================================================================
#define FBR 128
#define FBC 64
#define QST 68
#define KST 68
#define VST 72
#define F2_QS 0
#define F2_KS (FBR * QST)                 // 8704
#define F2_VS (F2_KS + FBC * KST)         // +4352
#define F2_PS (F2_VS + FBC * VST)         // +4608
#define F2_FLOATS (F2_PS + FBR * QST)     // +8704 = 26368
#define F2_SMEM_BYTES (F2_FLOATS * 4)     // 105472 B

__global__ __launch_bounds__(256, 2)
void flash2(const float* __restrict__ Q, const float* __restrict__ K,
            const float* __restrict__ V, float* __restrict__ AO) {
    extern __shared__ float smf[];
    uint32_t* Qs = (uint32_t*)(smf + F2_QS);
    uint32_t* Ks = (uint32_t*)(smf + F2_KS);
    uint32_t* Vs = (uint32_t*)(smf + F2_VS);
    uint32_t* Ps = (uint32_t*)(smf + F2_PS);

    const int tid = threadIdx.x;
    const int warp = tid >> 5, lane = tid & 31;
    const int g = lane >> 2, tg = lane & 3;
    const int qb = gridDim.x - 1 - blockIdx.x;   // long CTAs first
    const int bh = blockIdx.y;
    const int b = bh >> 5, h = bh & 31, hk = h >> 2;
    const int q0 = qb * FBR;
    const int strip = warp * 16;

    // Load Q tile (rows q0..q0+127), cvt tf32, Qs[r][d]
    {
        int r = tid >> 1;
        int d0 = (tid & 1) * 32;
        const float* Qg = Q + ((size_t)(b * TT + q0 + r) * HH + h) * DDIM + d0;
#pragma unroll
        for (int i = 0; i < 8; i++) {
            float4 v = *(const float4*)(Qg + i * 4);
            uint32_t* dst = &Qs[r * QST + d0 + i * 4];
            dst[0] = f2tf32(v.x); dst[1] = f2tf32(v.y);
            dst[2] = f2tf32(v.z); dst[3] = f2tf32(v.w);
        }
    }

    float m_[2] = {-1e30f, -1e30f};
    float l_[2] = {0.f, 0.f};
    float o_[8][4];
#pragma unroll
    for (int nt = 0; nt < 8; nt++)
#pragma unroll
        for (int v = 0; v < 4; v++) o_[nt][v] = 0.f;

    const int r0 = q0 + strip + g;          // this thread's lower row
    const float cscale = 0.125f * 1.44269504089f;  // log2(e)/sqrt(64)
    const int nkv = 2 * qb + 2;

    for (int kb = 0; kb < nkv; kb++) {
        const int k0 = kb * FBC;
        __syncthreads();   // prior iteration's Ks/Vs reads done
        {
            int r = tid >> 2;
            int d0 = (tid & 3) * 16;
            const float* Kg = K + ((size_t)(b * TT + k0 + r) * HKVN + hk) * DDIM + d0;
            const float* Vg = V + ((size_t)(b * TT + k0 + r) * HKVN + hk) * DDIM + d0;
#pragma unroll
            for (int i = 0; i < 4; i++) {
                float4 kv = *(const float4*)(Kg + i * 4);
                uint32_t* kd = &Ks[r * KST + d0 + i * 4];
                kd[0] = f2tf32(kv.x); kd[1] = f2tf32(kv.y);
                kd[2] = f2tf32(kv.z); kd[3] = f2tf32(kv.w);
                float4 vv = *(const float4*)(Vg + i * 4);
                uint32_t* vd = &Vs[r * VST + d0 + i * 4];
                vd[0] = f2tf32(vv.x); vd[1] = f2tf32(vv.y);
                vd[2] = f2tf32(vv.z); vd[3] = f2tf32(vv.w);
            }
        }
        __syncthreads();

        // ---- S = Q K^T : warp computes 16x64 strip ----
        float s[8][4];
#pragma unroll
        for (int nt = 0; nt < 8; nt++)
#pragma unroll
            for (int v = 0; v < 4; v++) s[nt][v] = 0.f;

#pragma unroll
        for (int ks = 0; ks < 8; ks++) {
            uint32_t a[4];
            const uint32_t* qp = &Qs[(strip + g) * QST + ks * 8 + tg];
            a[0] = qp[0];
            a[1] = qp[8 * QST];
            a[2] = qp[4];
            a[3] = qp[8 * QST + 4];
#pragma unroll
            for (int nt = 0; nt < 8; nt++) {
                uint32_t bfr[2];
                const uint32_t* kp = &Ks[(nt * 8 + g) * KST + ks * 8 + tg];
                bfr[0] = kp[0];
                bfr[1] = kp[4];
                mma_tf32(s[nt], a, bfr);
            }
        }

        // ---- online softmax (FMA-pipe exp2) ----
        const bool needmask = (kb >= nkv - 2);
        float mx0 = -1e30f, mx1 = -1e30f;
#pragma unroll
        for (int nt = 0; nt < 8; nt++) {
#pragma unroll
            for (int v = 0; v < 4; v++) {
                float val = s[nt][v] * cscale;
                if (needmask) {
                    int row = r0 + (v >> 1) * 8;
                    int col = k0 + nt * 8 + 2 * tg + (v & 1);
                    if (col > row) val = -1e30f;
                }
                s[nt][v] = val;
                if (v < 2) mx0 = fmaxf(mx0, val);
                else       mx1 = fmaxf(mx1, val);
            }
        }
        mx0 = fmaxf(mx0, __shfl_xor_sync(0xffffffffu, mx0, 1));
        mx0 = fmaxf(mx0, __shfl_xor_sync(0xffffffffu, mx0, 2));
        mx1 = fmaxf(mx1, __shfl_xor_sync(0xffffffffu, mx1, 1));
        mx1 = fmaxf(mx1, __shfl_xor_sync(0xffffffffu, mx1, 2));

        float mn0 = fmaxf(m_[0], mx0);
        float mn1 = fmaxf(m_[1], mx1);
        float al0 = fexp2(m_[0] - mn0);
        float al1 = fexp2(m_[1] - mn1);
        m_[0] = mn0; m_[1] = mn1;

        float rs0 = 0.f, rs1 = 0.f;
#pragma unroll
        for (int nt = 0; nt < 8; nt++) {
            float p0 = fexp2(s[nt][0] - mn0);
            float p1 = fexp2(s[nt][1] - mn0);
            float p2 = fexp2(s[nt][2] - mn1);
            float p3 = fexp2(s[nt][3] - mn1);
            rs0 += p0 + p1;
            rs1 += p2 + p3;
            uint32_t* pl = &Ps[(strip + g) * QST + nt * 8 + 2 * tg];
            pl[0] = f2tf32(p0);
            pl[1] = f2tf32(p1);
            pl[8 * QST] = f2tf32(p2);
            pl[8 * QST + 1] = f2tf32(p3);
        }
        rs0 += __shfl_xor_sync(0xffffffffu, rs0, 1);
        rs0 += __shfl_xor_sync(0xffffffffu, rs0, 2);
        rs1 += __shfl_xor_sync(0xffffffffu, rs1, 1);
        rs1 += __shfl_xor_sync(0xffffffffu, rs1, 2);
        l_[0] = l_[0] * al0 + rs0;
        l_[1] = l_[1] * al1 + rs1;

#pragma unroll
        for (int nt = 0; nt < 8; nt++) {
            o_[nt][0] *= al0;
            o_[nt][1] *= al0;
            o_[nt][2] *= al1;
            o_[nt][3] *= al1;
        }
        __syncwarp();   // Ps is warp-private: only intra-warp visibility needed

        // ---- O += P V ----
#pragma unroll
        for (int ks = 0; ks < 8; ks++) {
            uint32_t a[4];
            const uint32_t* pp = &Ps[(strip + g) * QST + ks * 8 + tg];
            a[0] = pp[0];
            a[1] = pp[8 * QST];
            a[2] = pp[4];
            a[3] = pp[8 * QST + 4];
#pragma unroll
            for (int nt = 0; nt < 8; nt++) {
                uint32_t bfr[2];
                bfr[0] = Vs[(ks * 8 + tg) * VST + nt * 8 + g];
                bfr[1] = Vs[(ks * 8 + tg + 4) * VST + nt * 8 + g];
                mma_tf32(o_[nt], a, bfr);
            }
        }
    }

    // ---- epilogue: normalize, write AO[b, t, h*64+d] ----
    float inv0 = 1.0f / l_[0];
    float inv1 = 1.0f / l_[1];
#pragma unroll
    for (int nt = 0; nt < 8; nt++) {
        int c0 = h * 64 + nt * 8 + 2 * tg;
        float* p0 = AO + (size_t)(b * TT + r0) * CC + c0;
        *(float2*)p0 = make_float2(o_[nt][0] * inv0, o_[nt][1] * inv0);
        float* p1 = AO + (size_t)(b * TT + r0 + 8) * CC + c0;
        *(float2*)p1 = make_float2(o_[nt][2] * inv1, o_[nt][3] * inv1);
    }
}

// ---------------------------------------------------------------------------
extern "C" void kernel_launch(void* const* d_in, const int* in_sizes, int n_in,
                              void* d_out, int out_size) {
    const float* x  = (const float*)d_in[0];
    const float* Wq = (const float*)d_in[1];
    const float* Wk = (const float*)d_in[2];
    const float* Wv = (const float*)d_in[3];
    const float* Wo = (const float*)d_in[4];
    float* out = (float*)d_out;

    float *pQ, *pK, *pV, *pAO;
    cudaGetSymbolAddress((void**)&pQ,  g_Q);
    cudaGetSymbolAddress((void**)&pK,  g_K);
    cudaGetSymbolAddress((void**)&pV,  g_V);
    cudaGetSymbolAddress((void**)&pAO, g_AO);

    cudaFuncSetAttribute(gemm_tf32, cudaFuncAttributeMaxDynamicSharedMemorySize,
                         GEMM_SMEM_BYTES);
    cudaFuncSetAttribute(flash2, cudaFuncAttributeMaxDynamicSharedMemorySize,
                         F2_SMEM_BYTES);

    dim3 blk(256);
    // QKV projections (tensor cores, tf32)
    gemm_tf32<<<dim3(16, 32), blk, GEMM_SMEM_BYTES>>>(x, Wq, pQ, BD * TT, CC, CC);
    gemm_tf32<<<dim3(4, 32),  blk, GEMM_SMEM_BYTES>>>(x, Wk, pK, BD * TT, HKVN * DDIM, CC);
    gemm_tf32<<<dim3(4, 32),  blk, GEMM_SMEM_BYTES>>>(x, Wv, pV, BD * TT, HKVN * DDIM, CC);

    // RoPE
    int totQ = BD * TT * HH * 32;
    int totK = BD * TT * HKVN * 32;
    rope_kernel<<<(totQ + 255) / 256, 256>>>(pQ, HH, totQ);
    rope_kernel<<<(totK + 255) / 256, 256>>>(pK, HKVN, totK);

    // Tensor-core causal flash attention
    flash2<<<dim3(TT / FBR, BD * HH), blk, F2_SMEM_BYTES>>>(pQ, pK, pV, pAO);

    // Output projection
    gemm_tf32<<<dim3(16, 32), blk, GEMM_SMEM_BYTES>>>(pAO, Wo, out, BD * TT, CC, CC);
}